// round 3
// baseline (speedup 1.0000x reference)
#include <cuda_runtime.h>

#define NR      96
#define DIM     768
#define TRIU    4560
#define P_CNT   9120
#define Q_CNT   9216
#define THR     0.3f
#define NSPLIT  48            // K splits of 16
#define KS      16
#define ELEMS   (3 * Q_CNT)   // 27648 partial elements per split
#define GRID_N  144
#define NTHR    512
#define NEG_SL  8
#define NEG_PER 1152
#define POS_GR  18

// ---------------- device scratch ----------------
__device__ float g_inv[2 * NR];
__device__ float g_part[NSPLIT * ELEMS];
__device__ float g_neg[Q_CNT];
__device__ float g_pos[P_CNT];
__device__ float g_sumP[GRID_N];
__device__ float g_sumN[GRID_N];
__device__ float g_blockSum[GRID_N];
__device__ unsigned g_bar_cnt = 0;
__device__ unsigned g_bar_gen = 0;

// ---------------- helpers ----------------
__device__ __forceinline__ unsigned long long addx2(unsigned long long a,
                                                    unsigned long long b) {
    unsigned long long r;
    asm("add.rn.f32x2 %0, %1, %2;" : "=l"(r) : "l"(a), "l"(b));
    return r;
}
#define ABSMASK 0x7fffffff7fffffffULL

__device__ __forceinline__ int triu_idx(int i, int j) {
    return i * (191 - i) / 2 + (j - i - 1);
}

// generation-counting grid barrier; counters self-reset (wrap) across runs
__device__ __forceinline__ void grid_bar() {
    __threadfence();
    __syncthreads();
    if (threadIdx.x == 0) {
        unsigned gen = atomicAdd(&g_bar_gen, 0u);
        unsigned old = atomicInc(&g_bar_cnt, GRID_N - 1);
        if (old == GRID_N - 1) {
            atomicAdd(&g_bar_gen, 1u);
        } else {
            while (*((volatile unsigned*)&g_bar_gen) == gen) { __nanosleep(64); }
        }
    }
    __syncthreads();
    __threadfence();
}

__device__ __forceinline__ float blockReduce512(float v, float* sbuf16) {
    __syncthreads();
    int t = threadIdx.x;
    #pragma unroll
    for (int o = 16; o; o >>= 1) v += __shfl_down_sync(0xffffffffu, v, o);
    if ((t & 31) == 0) sbuf16[t >> 5] = v;
    __syncthreads();
    float r = 0.f;
    if (t < 16) {
        r = sbuf16[t];
        #pragma unroll
        for (int o = 8; o; o >>= 1) r += __shfl_down_sync(0xffffu, r, o);
    }
    return r;   // valid at t == 0
}

// ---------------- the one kernel ----------------
__global__ void __launch_bounds__(NTHR, 1)
k_all(const float* __restrict__ S, const float* __restrict__ A,
      float* __restrict__ out) {
    __shared__ __align__(16) float pool[2 * KS * 98];   // 3136 floats
    __shared__ float sbuf[16];

    const int bid = blockIdx.x;
    const int t   = threadIdx.x;

    // ===== Phase A: inverse row norms (rows bid and bid+144) =====
    #pragma unroll
    for (int rr = 0; rr < 2; rr++) {
        int row = bid + rr * GRID_N;
        if (row < 2 * NR) {
            const float* src = (row < NR) ? (S + row * DIM) : (A + (row - NR) * DIM);
            float x0 = src[t];
            float x1 = (t < 256) ? src[512 + t] : 0.f;
            float r = blockReduce512(x0 * x0 + x1 * x1, sbuf);
            if (t == 0) g_inv[row] = 1.0f / fmaxf(sqrtf(r), 1e-8f);
        }
    }
    grid_bar();

    // ===== Phase B: gram partials. job = (mat, sk); full 96x96, K=16 =====
    {
        int mat = bid % 3;            // 0: neg = A x S^T, 1: S x S^T, 2: A x A^T
        int sk  = bid / 3;            // 0..47
        const float* Am = (mat == 1) ? S : A;
        const float* Bm = (mat == 2) ? A : S;
        int invAo = (mat == 1) ? 0 : NR;
        int invBo = (mat == 2) ? NR : 0;

        float* As = pool;               // [KS][98], As[k][row]
        float* Bs = pool + KS * 98;     // [KS][98], Bs[k][col]

        #pragma unroll
        for (int p = 0; p < 3; p++) {
            int lin = t + p * NTHR;     // 0..1535
            int row = lin >> 4;
            int kk  = lin & 15;
            int go  = row * DIM + sk * KS + kk;
            As[kk * 98 + row] = Am[go] * g_inv[invAo + row];
            Bs[kk * 98 + row] = Bm[go] * g_inv[invBo + row];
        }
        __syncthreads();

        int lane = t & 31;              // col base
        int ty   = t >> 5;              // 0..15 -> rows 6ty..6ty+5
        float acc[6][3];
        #pragma unroll
        for (int r = 0; r < 6; r++)
            #pragma unroll
            for (int c = 0; c < 3; c++) acc[r][c] = 0.f;

        #pragma unroll
        for (int k = 0; k < KS; k++) {
            float a[6];
            #pragma unroll
            for (int r = 0; r < 6; r++) a[r] = As[k * 98 + 6 * ty + r];
            float b0 = Bs[k * 98 + lane];
            float b1 = Bs[k * 98 + lane + 32];
            float b2 = Bs[k * 98 + lane + 64];
            #pragma unroll
            for (int r = 0; r < 6; r++) {
                acc[r][0] += a[r] * b0;
                acc[r][1] += a[r] * b1;
                acc[r][2] += a[r] * b2;
            }
        }

        float* dst = g_part + sk * ELEMS + mat * Q_CNT;
        #pragma unroll
        for (int r = 0; r < 6; r++) {
            int row = 6 * ty + r;
            #pragma unroll
            for (int c = 0; c < 3; c++) {
                int col = lane + 32 * c;
                if (mat == 0 || row < col)          // pos: only triu needed
                    dst[row * 96 + col] = acc[r][c];
            }
        }
    }
    grid_bar();

    // ===== Phase B2: combine split-K partials (fixed order) =====
    {
        float nv = 0.f, pv = 0.f;
        if (t < 192) {
            int e   = bid * 192 + t;                // 0..27647
            int mat = e / Q_CNT;
            int em  = e % Q_CNT;
            int r   = em / 96, c = em % 96;
            bool live = (mat == 0) || (r < c);
            if (live) {
                float s0 = 0.f, s1 = 0.f, s2 = 0.f, s3 = 0.f;
                #pragma unroll
                for (int sk = 0; sk < NSPLIT; sk += 4) {
                    s0 += g_part[(sk + 0) * ELEMS + e];
                    s1 += g_part[(sk + 1) * ELEMS + e];
                    s2 += g_part[(sk + 2) * ELEMS + e];
                    s3 += g_part[(sk + 3) * ELEMS + e];
                }
                float v = (s0 + s1) + (s2 + s3);
                if (mat == 0) { g_neg[em] = v; nv = v; }
                else {
                    g_pos[((mat == 1) ? 0 : TRIU) + triu_idx(r, c)] = v;
                    pv = v;
                }
            }
        }
        float rn = blockReduce512(nv, sbuf);
        if (t == 0) g_sumN[bid] = rn;
        float rp = blockReduce512(pv, sbuf);
        if (t == 0) g_sumP[bid] = rp;
    }
    grid_bar();

    // ===== Phase C: hinge sum |n - p + thr|, packed f32x2 =====
    {
        float* s_neg = pool;                    // 1152 floats
        int ns = bid / POS_GR;                  // 0..7
        int pg = bid % POS_GR;                  // 0..17
        int j0 = ns * NEG_PER;
        for (int j = t; j < NEG_PER; j += NTHR) s_neg[j] = g_neg[j0 + j];
        __syncthreads();

        float acc = 0.f;
        int pid = pg * NTHR + t;
        if (pid < P_CNT) {
            float cc = THR - g_pos[pid];
            unsigned cu = __float_as_uint(cc);
            unsigned long long c2 = ((unsigned long long)cu << 32) | cu;
            const ulonglong2* sn = reinterpret_cast<const ulonglong2*>(s_neg);
            unsigned long long a0 = 0ull, a1 = 0ull, a2 = 0ull, a3 = 0ull;
            #pragma unroll 8
            for (int i = 0; i < NEG_PER / 8; i++) {
                ulonglong2 v0 = sn[2 * i];
                ulonglong2 v1 = sn[2 * i + 1];
                a0 = addx2(a0, addx2(v0.x, c2) & ABSMASK);
                a1 = addx2(a1, addx2(v0.y, c2) & ABSMASK);
                a2 = addx2(a2, addx2(v1.x, c2) & ABSMASK);
                a3 = addx2(a3, addx2(v1.y, c2) & ABSMASK);
            }
            float s01 = (__uint_as_float((unsigned)a0) + __uint_as_float((unsigned)(a0 >> 32)))
                      + (__uint_as_float((unsigned)a1) + __uint_as_float((unsigned)(a1 >> 32)));
            float s23 = (__uint_as_float((unsigned)a2) + __uint_as_float((unsigned)(a2 >> 32)))
                      + (__uint_as_float((unsigned)a3) + __uint_as_float((unsigned)(a3 >> 32)));
            acc = s01 + s23;
        }
        float bsum = blockReduce512(acc, sbuf);
        if (t == 0) g_blockSum[bid] = bsum;
    }
    grid_bar();

    // ===== Phase D: block 0 final combine =====
    if (bid != 0) return;
    float vA = (t < GRID_N) ? g_blockSum[t] : 0.f;
    float S_abs = blockReduce512(vA, sbuf);
    float vP = (t < GRID_N) ? g_sumP[t] : 0.f;
    float S_pos = blockReduce512(vP, sbuf);
    float vN = (t < GRID_N) ? g_sumN[t] : 0.f;
    float S_neg = blockReduce512(vN, sbuf);

    if (t == 0) {
        const double P = (double)P_CNT, Q = (double)Q_CNT, thr = (double)THR;
        double Sx = P * (double)S_neg - Q * (double)S_pos + P * Q * thr;
        out[0] = (float)(0.5 * (Sx + (double)S_abs) / (P * Q));
    }
}

// ---------------- launch ----------------
extern "C" void kernel_launch(void* const* d_in, const int* in_sizes, int n_in,
                              void* d_out, int out_size) {
    const float* stereos  = (const float*)d_in[0];
    const float* astereos = (const float*)d_in[1];
    k_all<<<GRID_N, NTHR>>>(stereos, astereos, (float*)d_out);
}

// round 4
// speedup vs baseline: 1.1758x; 1.1758x over previous
#include <cuda_runtime.h>

#define NR      96
#define DIM     768
#define TRIU    4560
#define P_CNT   9120
#define Q_CNT   9216
#define THR     0.3f
#define SPLITK  8              // 768/8 = 96 per split
#define NEG_SL  8
#define NEG_PER 1152
#define POS_GR  18
#define HB      (NEG_SL * POS_GR)   // 144

// ---------------- device scratch ----------------
__device__ float g_partPos[SPLITK * P_CNT];
__device__ float g_partNeg[SPLITK * Q_CNT];
__device__ float g_partDiag[SPLITK * 2 * NR];
__device__ float g_blockSum[HB];
__device__ float g_posSum[POS_GR];
__device__ float g_negSum[NEG_SL];
__device__ unsigned g_count = 0;

// ---------------- helpers ----------------
__device__ __forceinline__ unsigned long long addx2(unsigned long long a,
                                                    unsigned long long b) {
    unsigned long long r;
    asm("add.rn.f32x2 %0, %1, %2;" : "=l"(r) : "l"(a), "l"(b));
    return r;
}
#define ABSMASK 0x7fffffff7fffffffULL

__device__ __forceinline__ int triu_base(int i) { return i * (191 - i) / 2; }
__device__ __forceinline__ int triu_idx(int i, int j) {
    return triu_base(i) + (j - i - 1);
}

__device__ __forceinline__ float blockReduce512(float v, float* sbuf16) {
    __syncthreads();
    int t = threadIdx.x;
    #pragma unroll
    for (int o = 16; o; o >>= 1) v += __shfl_down_sync(0xffffffffu, v, o);
    if ((t & 31) == 0) sbuf16[t >> 5] = v;
    __syncthreads();
    float r = 0.f;
    if (t < 16) {
        r = sbuf16[t];
        #pragma unroll
        for (int o = 8; o; o >>= 1) r += __shfl_down_sync(0xffffu, r, o);
    }
    return r;   // valid at t == 0
}

// ---------------- K1: RAW grams + diag partials (168 blocks x 256) --------
__global__ void __launch_bounds__(256) k_gram(const float* __restrict__ S,
                                              const float* __restrict__ A) {
    __shared__ float As[32][34];
    __shared__ float Bs[32][34];

    int bx = blockIdx.x;
    int sk = bx / 21;
    int tl = bx % 21;

    int m, tr, tc;
    if (tl < 9) { m = 0; tr = tl / 3; tc = tl % 3; }
    else {
        int q = tl - 9;
        m = 1 + q / 6;
        const int TR6[6] = {0,0,0,1,1,2};
        const int TC6[6] = {0,1,2,1,2,2};
        tr = TR6[q % 6]; tc = TC6[q % 6];
    }
    // m0: neg = A x S^T; m1: S x S^T; m2: A x A^T
    const float* Ap = (m == 1) ? S : A;
    const float* Bp = (m == 2) ? A : S;

    int t  = threadIdx.x;
    int tx = t & 15, ty = t >> 4;

    float acc00 = 0.f, acc01 = 0.f, acc10 = 0.f, acc11 = 0.f;

    for (int ch = 0; ch < 3; ch++) {
        int kb = sk * 96 + ch * 32;
        __syncthreads();
        #pragma unroll
        for (int p = 0; p < 4; p++) {
            int lin = t + p * 256;
            int kk  = lin & 31, row = lin >> 5;
            As[kk][row] = Ap[(tr * 32 + row) * DIM + kb + kk];
            Bs[kk][row] = Bp[(tc * 32 + row) * DIM + kb + kk];
        }
        __syncthreads();
        #pragma unroll
        for (int kk = 0; kk < 32; kk++) {
            float2 a = *(const float2*)&As[kk][2 * ty];
            float2 b = *(const float2*)&Bs[kk][2 * tx];
            acc00 += a.x * b.x; acc01 += a.x * b.y;
            acc10 += a.y * b.x; acc11 += a.y * b.y;
        }
    }

    int r0 = tr * 32 + 2 * ty;
    int c0 = tc * 32 + 2 * tx;
    if (m == 0) {
        float* dst = g_partNeg + sk * Q_CNT;
        dst[r0 * 96 + c0]           = acc00;
        dst[r0 * 96 + c0 + 1]       = acc01;
        dst[(r0 + 1) * 96 + c0]     = acc10;
        dst[(r0 + 1) * 96 + c0 + 1] = acc11;
    } else {
        float* dst = g_partPos + sk * P_CNT + ((m == 2) ? TRIU : 0);
        if (r0     < c0    ) dst[triu_idx(r0,     c0    )] = acc00;
        if (r0     < c0 + 1) dst[triu_idx(r0,     c0 + 1)] = acc01;
        if (r0 + 1 < c0    ) dst[triu_idx(r0 + 1, c0    )] = acc10;
        if (r0 + 1 < c0 + 1) dst[triu_idx(r0 + 1, c0 + 1)] = acc11;
        if (r0 == c0) {  // diagonal entries -> squared row norms
            int off = (m == 1) ? 0 : NR;
            g_partDiag[sk * 2 * NR + off + r0]     = acc00;
            g_partDiag[sk * 2 * NR + off + r0 + 1] = acc11;
        }
    }
}

// ---------------- K2: normalize + hinge + fused final (144 x 512) ---------
__global__ void __launch_bounds__(512) k_hinge(float* __restrict__ out) {
    __shared__ __align__(16) float s_neg[NEG_PER];
    __shared__ float s_inv[2 * NR];
    __shared__ float sbuf[16];
    __shared__ bool s_last;

    int bid = blockIdx.x;
    int ns  = bid / POS_GR;       // 0..7
    int pg  = bid % POS_GR;       // 0..17
    int t   = threadIdx.x;

    // --- combine diag partials -> inverse norms (s_inv[0..95]=S, 96..191=A)
    if (t < 2 * NR) {
        float d = ((g_partDiag[0 * 192 + t] + g_partDiag[1 * 192 + t]) +
                   (g_partDiag[2 * 192 + t] + g_partDiag[3 * 192 + t])) +
                  ((g_partDiag[4 * 192 + t] + g_partDiag[5 * 192 + t]) +
                   (g_partDiag[6 * 192 + t] + g_partDiag[7 * 192 + t]));
        s_inv[t] = 1.0f / fmaxf(sqrtf(d), 1e-8f);
    }
    __syncthreads();

    // --- combine + normalize this block's neg slice into smem
    int j0 = ns * NEG_PER;
    for (int j = t; j < NEG_PER; j += 512) {
        int gj = j0 + j;
        float raw = ((g_partNeg[0 * Q_CNT + gj] + g_partNeg[1 * Q_CNT + gj]) +
                     (g_partNeg[2 * Q_CNT + gj] + g_partNeg[3 * Q_CNT + gj])) +
                    ((g_partNeg[4 * Q_CNT + gj] + g_partNeg[5 * Q_CNT + gj]) +
                     (g_partNeg[6 * Q_CNT + gj] + g_partNeg[7 * Q_CNT + gj]));
        int r = gj / 96, c = gj % 96;
        s_neg[j] = raw * s_inv[NR + r] * s_inv[c];
    }

    // --- combine + normalize this thread's pos value
    int pid = pg * 512 + t;
    bool act = (pid < P_CNT);
    float posv = 0.f;
    if (act) {
        float raw = ((g_partPos[0 * P_CNT + pid] + g_partPos[1 * P_CNT + pid]) +
                     (g_partPos[2 * P_CNT + pid] + g_partPos[3 * P_CNT + pid])) +
                    ((g_partPos[4 * P_CNT + pid] + g_partPos[5 * P_CNT + pid]) +
                     (g_partPos[6 * P_CNT + pid] + g_partPos[7 * P_CNT + pid]));
        int invo = (pid < TRIU) ? 0 : NR;
        int p    = (pid < TRIU) ? pid : (pid - TRIU);
        // invert triu packing: largest i with i*(191-i)/2 <= p
        int i = (int)((191.0 - sqrt(36481.0 - 8.0 * (double)p)) * 0.5);
        while (triu_base(i + 1) <= p) ++i;
        while (triu_base(i) > p)      --i;
        int j = p - triu_base(i) + i + 1;
        posv = raw * s_inv[invo + i] * s_inv[invo + j];
    }
    __syncthreads();

    // --- designated blocks record separable sums
    if (ns == 0) {
        float r = blockReduce512(act ? posv : 0.f, sbuf);
        if (t == 0) g_posSum[pg] = r;
    }
    if (pg == 0) {
        float v = s_neg[t] + s_neg[t + 512] + ((t < 128) ? s_neg[t + 1024] : 0.f);
        float r = blockReduce512(v, sbuf);
        if (t == 0) g_negSum[ns] = r;
    }

    // --- main hinge: sum |n - p + thr| over slice, packed f32x2
    float acc = 0.f;
    if (act) {
        float cc = THR - posv;
        unsigned cu = __float_as_uint(cc);
        unsigned long long c2 = ((unsigned long long)cu << 32) | cu;
        const ulonglong2* sn = reinterpret_cast<const ulonglong2*>(s_neg);
        unsigned long long a0 = 0ull, a1 = 0ull, a2 = 0ull, a3 = 0ull;
        #pragma unroll 8
        for (int i = 0; i < NEG_PER / 8; i++) {
            ulonglong2 v0 = sn[2 * i];
            ulonglong2 v1 = sn[2 * i + 1];
            a0 = addx2(a0, addx2(v0.x, c2) & ABSMASK);
            a1 = addx2(a1, addx2(v0.y, c2) & ABSMASK);
            a2 = addx2(a2, addx2(v1.x, c2) & ABSMASK);
            a3 = addx2(a3, addx2(v1.y, c2) & ABSMASK);
        }
        float s01 = (__uint_as_float((unsigned)a0) + __uint_as_float((unsigned)(a0 >> 32)))
                  + (__uint_as_float((unsigned)a1) + __uint_as_float((unsigned)(a1 >> 32)));
        float s23 = (__uint_as_float((unsigned)a2) + __uint_as_float((unsigned)(a2 >> 32)))
                  + (__uint_as_float((unsigned)a3) + __uint_as_float((unsigned)(a3 >> 32)));
        acc = s01 + s23;
    }
    float bsum = blockReduce512(acc, sbuf);
    if (t == 0) g_blockSum[bid] = bsum;

    // --- last-block-done deterministic final combine
    if (t == 0) {
        __threadfence();
        unsigned old = atomicInc(&g_count, HB - 1);
        s_last = (old == HB - 1);
    }
    __syncthreads();
    if (!s_last) return;
    __threadfence();

    float vA = (t < HB)     ? g_blockSum[t] : 0.f;
    float S_abs = blockReduce512(vA, sbuf);
    float vP = (t < POS_GR) ? g_posSum[t]   : 0.f;
    float S_pos = blockReduce512(vP, sbuf);
    float vN = (t < NEG_SL) ? g_negSum[t]   : 0.f;
    float S_neg = blockReduce512(vN, sbuf);

    if (t == 0) {
        const double P = (double)P_CNT, Q = (double)Q_CNT, thr = (double)THR;
        double Sx = P * (double)S_neg - Q * (double)S_pos + P * Q * thr;
        out[0] = (float)(0.5 * (Sx + (double)S_abs) / (P * Q));
    }
}

// ---------------- launch ----------------
extern "C" void kernel_launch(void* const* d_in, const int* in_sizes, int n_in,
                              void* d_out, int out_size) {
    const float* stereos  = (const float*)d_in[0];
    const float* astereos = (const float*)d_in[1];
    k_gram<<<21 * SPLITK, 256>>>(stereos, astereos);
    k_hinge<<<HB, 512>>>((float*)d_out);
}

// round 5
// speedup vs baseline: 1.1905x; 1.0125x over previous
#include <cuda_runtime.h>

#define NR      96
#define DIM     768
#define TRIU    4560
#define P_CNT   9120
#define Q_CNT   9216
#define THR     0.3f
#define SPLITK  8              // 768/8 = 96 per split
#define NEG_SL  8
#define NEG_PER 1152
#define POS_GR  18
#define HB      (NEG_SL * POS_GR)   // 144

// ---------------- device scratch ----------------
__device__ float g_partPos[SPLITK * P_CNT];
__device__ float g_partNeg[SPLITK * Q_CNT];
__device__ float g_partDiag[SPLITK * 2 * NR];
__device__ float g_blockSum[HB];
__device__ float g_posSum[POS_GR];
__device__ float g_negSum[NEG_SL];
__device__ unsigned g_count = 0;

// ---------------- helpers ----------------
__device__ __forceinline__ unsigned long long addx2(unsigned long long a,
                                                    unsigned long long b) {
    unsigned long long r;
    asm("add.rn.f32x2 %0, %1, %2;" : "=l"(r) : "l"(a), "l"(b));
    return r;
}
#define ABSMASK 0x7fffffff7fffffffULL

__device__ __forceinline__ int triu_base(int i) { return i * (191 - i) / 2; }
__device__ __forceinline__ int triu_idx(int i, int j) {
    return triu_base(i) + (j - i - 1);
}

__device__ __forceinline__ float blockReduce512(float v, float* sbuf16) {
    __syncthreads();
    int t = threadIdx.x;
    #pragma unroll
    for (int o = 16; o; o >>= 1) v += __shfl_down_sync(0xffffffffu, v, o);
    if ((t & 31) == 0) sbuf16[t >> 5] = v;
    __syncthreads();
    float r = 0.f;
    if (t < 16) {
        r = sbuf16[t];
        #pragma unroll
        for (int o = 8; o; o >>= 1) r += __shfl_down_sync(0xffffu, r, o);
    }
    return r;   // valid at t == 0
}

// ---------------- K1: RAW grams + diag partials (168 blocks x 256) --------
__global__ void __launch_bounds__(256) k_gram(const float* __restrict__ S,
                                              const float* __restrict__ A) {
    __shared__ float As[32][34];
    __shared__ float Bs[32][34];

    int bx = blockIdx.x;
    int sk = bx / 21;
    int tl = bx % 21;

    int m, tr, tc;
    if (tl < 9) { m = 0; tr = tl / 3; tc = tl % 3; }
    else {
        int q = tl - 9;
        m = 1 + q / 6;
        const int TR6[6] = {0,0,0,1,1,2};
        const int TC6[6] = {0,1,2,1,2,2};
        tr = TR6[q % 6]; tc = TC6[q % 6];
    }
    // m0: neg = A x S^T; m1: S x S^T; m2: A x A^T
    const float* Ap = (m == 1) ? S : A;
    const float* Bp = (m == 2) ? A : S;

    int t  = threadIdx.x;
    int tx = t & 15, ty = t >> 4;

    float acc00 = 0.f, acc01 = 0.f, acc10 = 0.f, acc11 = 0.f;

    for (int ch = 0; ch < 3; ch++) {
        int kb = sk * 96 + ch * 32;
        __syncthreads();
        #pragma unroll
        for (int p = 0; p < 4; p++) {
            int lin = t + p * 256;
            int kk  = lin & 31, row = lin >> 5;
            As[kk][row] = Ap[(tr * 32 + row) * DIM + kb + kk];
            Bs[kk][row] = Bp[(tc * 32 + row) * DIM + kb + kk];
        }
        __syncthreads();
        #pragma unroll
        for (int kk = 0; kk < 32; kk++) {
            float2 a = *(const float2*)&As[kk][2 * ty];
            float2 b = *(const float2*)&Bs[kk][2 * tx];
            acc00 += a.x * b.x; acc01 += a.x * b.y;
            acc10 += a.y * b.x; acc11 += a.y * b.y;
        }
    }

    int r0 = tr * 32 + 2 * ty;
    int c0 = tc * 32 + 2 * tx;
    if (m == 0) {
        float* dst = g_partNeg + sk * Q_CNT;
        dst[r0 * 96 + c0]           = acc00;
        dst[r0 * 96 + c0 + 1]       = acc01;
        dst[(r0 + 1) * 96 + c0]     = acc10;
        dst[(r0 + 1) * 96 + c0 + 1] = acc11;
    } else {
        float* dst = g_partPos + sk * P_CNT + ((m == 2) ? TRIU : 0);
        if (r0     < c0    ) dst[triu_idx(r0,     c0    )] = acc00;
        if (r0     < c0 + 1) dst[triu_idx(r0,     c0 + 1)] = acc01;
        if (r0 + 1 < c0    ) dst[triu_idx(r0 + 1, c0    )] = acc10;
        if (r0 + 1 < c0 + 1) dst[triu_idx(r0 + 1, c0 + 1)] = acc11;
        if (r0 == c0) {  // diagonal entries -> squared row norms
            int off = (m == 1) ? 0 : NR;
            g_partDiag[sk * 2 * NR + off + r0]     = acc00;
            g_partDiag[sk * 2 * NR + off + r0 + 1] = acc11;
        }
    }
}

// ---------------- K2: normalize + hinge + fused final (144 x 512) ---------
__global__ void __launch_bounds__(512, 1) k_hinge(float* __restrict__ out) {
    __shared__ __align__(16) float s_neg[NEG_PER];
    __shared__ float s_inv[2 * NR];
    __shared__ float sbuf[16];
    __shared__ bool s_last;

    int bid = blockIdx.x;
    int ns  = bid / POS_GR;       // 0..7
    int pg  = bid % POS_GR;       // 0..17
    int t   = threadIdx.x;

    // --- combine diag partials -> inverse norms (s_inv[0..95]=S, 96..191=A)
    if (t < 2 * NR) {
        float d = ((g_partDiag[0 * 192 + t] + g_partDiag[1 * 192 + t]) +
                   (g_partDiag[2 * 192 + t] + g_partDiag[3 * 192 + t])) +
                  ((g_partDiag[4 * 192 + t] + g_partDiag[5 * 192 + t]) +
                   (g_partDiag[6 * 192 + t] + g_partDiag[7 * 192 + t]));
        s_inv[t] = 1.0f / fmaxf(sqrtf(d), 1e-8f);
    }
    __syncthreads();

    // --- combine + normalize this block's neg slice into smem
    int j0 = ns * NEG_PER;
    for (int j = t; j < NEG_PER; j += 512) {
        int gj = j0 + j;
        float raw = ((g_partNeg[0 * Q_CNT + gj] + g_partNeg[1 * Q_CNT + gj]) +
                     (g_partNeg[2 * Q_CNT + gj] + g_partNeg[3 * Q_CNT + gj])) +
                    ((g_partNeg[4 * Q_CNT + gj] + g_partNeg[5 * Q_CNT + gj]) +
                     (g_partNeg[6 * Q_CNT + gj] + g_partNeg[7 * Q_CNT + gj]));
        int r = gj / 96, c = gj % 96;
        s_neg[j] = raw * s_inv[NR + r] * s_inv[c];
    }

    // --- combine + normalize this thread's pos value
    int pid = pg * 512 + t;
    bool act = (pid < P_CNT);
    float posv = 0.f;
    if (act) {
        float raw = ((g_partPos[0 * P_CNT + pid] + g_partPos[1 * P_CNT + pid]) +
                     (g_partPos[2 * P_CNT + pid] + g_partPos[3 * P_CNT + pid])) +
                    ((g_partPos[4 * P_CNT + pid] + g_partPos[5 * P_CNT + pid]) +
                     (g_partPos[6 * P_CNT + pid] + g_partPos[7 * P_CNT + pid]));
        int invo = (pid < TRIU) ? 0 : NR;
        int p    = (pid < TRIU) ? pid : (pid - TRIU);
        int i = (int)((191.0 - sqrt(36481.0 - 8.0 * (double)p)) * 0.5);
        while (triu_base(i + 1) <= p) ++i;
        while (triu_base(i) > p)      --i;
        int j = p - triu_base(i) + i + 1;
        posv = raw * s_inv[invo + i] * s_inv[invo + j];
    }
    __syncthreads();

    // --- designated blocks record separable sums
    if (ns == 0) {
        float r = blockReduce512(act ? posv : 0.f, sbuf);
        if (t == 0) g_posSum[pg] = r;
    }
    if (pg == 0) {
        float v = s_neg[t] + s_neg[t + 512] + ((t < 128) ? s_neg[t + 1024] : 0.f);
        float r = blockReduce512(v, sbuf);
        if (t == 0) g_negSum[ns] = r;
    }

    // --- main hinge: sum |n - p + thr|, packed f32x2, 8 chains, batched LDS
    float acc = 0.f;
    if (act) {
        float cc = THR - posv;
        unsigned cu = __float_as_uint(cc);
        unsigned long long c2 = ((unsigned long long)cu << 32) | cu;
        const ulonglong2* sn = reinterpret_cast<const ulonglong2*>(s_neg); // 288
        unsigned long long a0 = 0ull, a1 = 0ull, a2 = 0ull, a3 = 0ull;
        unsigned long long a4 = 0ull, a5 = 0ull, a6 = 0ull, a7 = 0ull;
        #pragma unroll 2
        for (int i = 0; i < 288; i += 4) {   // 16 negs per iter
            ulonglong2 v0 = sn[i];
            ulonglong2 v1 = sn[i + 1];
            ulonglong2 v2 = sn[i + 2];
            ulonglong2 v3 = sn[i + 3];
            a0 = addx2(a0, addx2(v0.x, c2) & ABSMASK);
            a1 = addx2(a1, addx2(v0.y, c2) & ABSMASK);
            a2 = addx2(a2, addx2(v1.x, c2) & ABSMASK);
            a3 = addx2(a3, addx2(v1.y, c2) & ABSMASK);
            a4 = addx2(a4, addx2(v2.x, c2) & ABSMASK);
            a5 = addx2(a5, addx2(v2.y, c2) & ABSMASK);
            a6 = addx2(a6, addx2(v3.x, c2) & ABSMASK);
            a7 = addx2(a7, addx2(v3.y, c2) & ABSMASK);
        }
        a0 = addx2(addx2(a0, a1), addx2(a2, a3));
        a4 = addx2(addx2(a4, a5), addx2(a6, a7));
        a0 = addx2(a0, a4);
        acc = __uint_as_float((unsigned)a0) + __uint_as_float((unsigned)(a0 >> 32));
    }
    float bsum = blockReduce512(acc, sbuf);
    if (t == 0) g_blockSum[bid] = bsum;

    // --- last-block-done deterministic final combine
    if (t == 0) {
        __threadfence();
        unsigned old = atomicInc(&g_count, HB - 1);
        s_last = (old == HB - 1);
    }
    __syncthreads();
    if (!s_last) return;
    __threadfence();

    float vA = (t < HB)     ? g_blockSum[t] : 0.f;
    float S_abs = blockReduce512(vA, sbuf);
    float vP = (t < POS_GR) ? g_posSum[t]   : 0.f;
    float S_pos = blockReduce512(vP, sbuf);
    float vN = (t < NEG_SL) ? g_negSum[t]   : 0.f;
    float S_neg = blockReduce512(vN, sbuf);

    if (t == 0) {
        const double P = (double)P_CNT, Q = (double)Q_CNT, thr = (double)THR;
        double Sx = P * (double)S_neg - Q * (double)S_pos + P * Q * thr;
        out[0] = (float)(0.5 * (Sx + (double)S_abs) / (P * Q));
    }
}

// ---------------- launch ----------------
extern "C" void kernel_launch(void* const* d_in, const int* in_sizes, int n_in,
                              void* d_out, int out_size) {
    const float* stereos  = (const float*)d_in[0];
    const float* astereos = (const float*)d_in[1];
    k_gram<<<21 * SPLITK, 256>>>(stereos, astereos);
    k_hinge<<<HB, 512>>>((float*)d_out);
}